// round 15
// baseline (speedup 1.0000x reference)
#include <cuda_runtime.h>
#include <cuda_fp16.h>
#include <math.h>
#include <stdint.h>

// ---------------- problem constants ----------------
#define BATCH 256
#define EDIM  512
#define VDIM  27000
#define VPAD  27008
#define LSTEPS 16
#define CMAX  200
#define KZ    1536
#define GDIM  2048

#define PLANE_B  ((size_t)VPAD * EDIM)
#define PLANE_W  ((size_t)GDIM * KZ)
#define PLANE_Z  ((size_t)BATCH * KZ)
#define PLANE_H  ((size_t)BATCH * EDIM)
#define PLANE_AW ((size_t)EDIM * EDIM)

#define NHW    32              // 8 n-tiles x 4 k-splits
#define NATTN  256
#define NLOG   (VPAD / 64)     // 422
#define NGATT  96              // 32 n-tiles x 3 k-splits (att+h part)
#define NEMBZ  32
#define NGEMB  64              // 32 n-tiles x 2 k-splits (emb part)
#define NLSTM  64
#define NGATES_ALL (NGATT + NGEMB)   // 160

// ---------------- persistent device scratch ----------------
__device__ __align__(128) float g_h[BATCH * EDIM];
__device__ __align__(128) float g_c[BATCH * EDIM];
__device__ __align__(128) float g_gatesP[5 * BATCH * GDIM];   // attth: 0..2, emb: 3..4
__device__ __align__(128) float g_hwP[4 * BATCH * EDIM];      // attn_W @ h partials
__device__ __align__(128) float g_bg[GDIM];
__device__ int   g_off[BATCH + 1];
__device__ unsigned long long g_amax[BATCH];
__device__ unsigned int g_sync[5];  // 0=hw 1=attn 2=logits 3=embz 4=gates
__device__ __align__(128) __half g_B2[2 * PLANE_B];           // proj_W^T limbs
__device__ __align__(128) __half g_W2[2 * PLANE_W];           // [W_ih|W_hh] limbs
__device__ __align__(128) __half g_z2[2 * PLANE_Z];           // z limbs
__device__ __align__(128) __half g_h2[2 * PLANE_H];           // h limbs
__device__ __align__(128) __half g_AW2[2 * PLANE_AW];         // attn_W limbs

// ---------------- helpers ----------------
__device__ __forceinline__ uint32_t smem_u32(const void* p) {
    uint32_t a;
    asm("{ .reg .u64 t; cvta.to.shared.u64 t, %1; cvt.u32.u64 %0, t; }" : "=r"(a) : "l"(p));
    return a;
}
__device__ __forceinline__ void split2_store(float v, __half* base, size_t off, size_t plane) {
    __half h = __float2half_rn(v);
    float r = v - __half2float(h);
    base[off]         = h;
    base[off + plane] = __float2half_rn(r);
}
__device__ __forceinline__ void ldmatrix_x4(uint32_t* r, uint32_t addr) {
    asm volatile("ldmatrix.sync.aligned.m8n8.x4.shared.b16 {%0,%1,%2,%3}, [%4];"
                 : "=r"(r[0]), "=r"(r[1]), "=r"(r[2]), "=r"(r[3]) : "r"(addr) : "memory");
}
__device__ __forceinline__ void mma16816(float* c, const uint32_t* a, uint32_t b0, uint32_t b1) {
    asm volatile(
        "mma.sync.aligned.m16n8k16.row.col.f32.f16.f16.f32 "
        "{%0,%1,%2,%3}, {%4,%5,%6,%7}, {%8,%9}, {%0,%1,%2,%3};"
        : "+f"(c[0]), "+f"(c[1]), "+f"(c[2]), "+f"(c[3])
        : "r"(a[0]), "r"(a[1]), "r"(a[2]), "r"(a[3]), "r"(b0), "r"(b1));
}
__device__ __forceinline__ void cp_async16(uint32_t dst, const void* src) {
    asm volatile("cp.async.cg.shared.global [%0], [%1], 16;" :: "r"(dst), "l"(src) : "memory");
}
#define CP_COMMIT() asm volatile("cp.async.commit_group;" ::: "memory")
#define CP_WAIT0()  asm volatile("cp.async.wait_group 0;" ::: "memory")
#define CP_WAIT1()  asm volatile("cp.async.wait_group 1;" ::: "memory")

__device__ __forceinline__ unsigned long long pack_key(float v, int col) {
    uint32_t u = __float_as_uint(v);
    u = (u & 0x80000000u) ? ~u : (u | 0x80000000u);
    return ((unsigned long long)u << 32) | (unsigned long long)(0x7FFFFFFFu - (uint32_t)col);
}

__device__ __forceinline__ void spin_until(volatile unsigned int* ctr, unsigned int target) {
    if (threadIdx.x == 0) {
        while (*ctr < target) __nanosleep(200);
    }
    __syncthreads();
    __threadfence();
}
__device__ __forceinline__ void signal_done(unsigned int* ctr) {
    __syncthreads();
    __threadfence();
    if (threadIdx.x == 0) atomicAdd(ctr, 1u);
}

// ---------------- init: offsets prefix sum + initial tokens + sync reset ----------------
__global__ void init_meta_kernel(const int* __restrict__ counts,
                                 const int* __restrict__ target_labels) {
    __shared__ int s[BATCH];
    int t = threadIdx.x;
    s[t] = counts[t];
    __syncthreads();
    for (int d = 1; d < BATCH; d <<= 1) {
        int v = (t >= d) ? s[t - d] : 0;
        __syncthreads();
        s[t] += v;
        __syncthreads();
    }
    g_off[t] = s[t] - counts[t];
    if (t == 0) g_off[BATCH] = s[BATCH - 1];
    if (t < 5) g_sync[t] = 0u;
    g_amax[t] = (unsigned long long)(0x7FFFFFFFu - (uint32_t)target_labels[t]);
}

// ---------------- prep kernels ----------------
__global__ void build_wg2_kernel(const float* __restrict__ W_ih,
                                 const float* __restrict__ W_hh,
                                 const float* __restrict__ b_ih,
                                 const float* __restrict__ b_hh) {
    int i = blockIdx.x * blockDim.x + threadIdx.x;
    if (i < GDIM * KZ) {
        int n = i / KZ, k = i % KZ;
        float v = (k < 1024) ? W_ih[(size_t)n * 1024 + k]
                             : W_hh[(size_t)n * 512 + (k - 1024)];
        split2_store(v, g_W2, (size_t)n * KZ + k, PLANE_W);
    }
    if (i < GDIM) g_bg[i] = b_ih[i] + b_hh[i];
}

__global__ void prepB2_kernel(const float* __restrict__ W) {
    __shared__ float tile[32][33];
    int n0 = blockIdx.x * 32, k0 = blockIdx.y * 32;
    int tx = threadIdx.x, ty = threadIdx.y;
#pragma unroll
    for (int i = 0; i < 4; i++) {
        int k = k0 + ty + i * 8, n = n0 + tx;
        tile[ty + i * 8][tx] = (n < VDIM) ? W[(size_t)k * VDIM + n] : 0.f;
    }
    __syncthreads();
#pragma unroll
    for (int i = 0; i < 4; i++)
        split2_store(tile[tx][ty + i * 8], g_B2,
                     (size_t)(n0 + ty + i * 8) * EDIM + k0 + tx, PLANE_B);
}

__global__ void prepAW2_kernel(const float* __restrict__ W) {
    int i = blockIdx.x * blockDim.x + threadIdx.x;
    if (i < EDIM * EDIM) split2_store(W[i], g_AW2, (size_t)i, PLANE_AW);
}

__global__ void init_h_kernel(const float* __restrict__ enc,
                              const int* __restrict__ counts) {
    int b = blockIdx.x, t = threadIdx.x;
    int cnt = counts[b], off = g_off[b];
    float2 acc = make_float2(0.f, 0.f);
    for (int c = 0; c < cnt; c++) {
        float2 v = *(const float2*)(enc + (size_t)(off + c) * EDIM + 2 * t);
        acc.x += v.x; acc.y += v.y;
    }
    float inv = 1.f / (float)cnt;
    float h0 = acc.x * inv, h1 = acc.y * inv;
    int i0 = b * EDIM + 2 * t, i1 = i0 + 1;
    g_h[i0] = h0;  g_c[i0] = h0;
    g_h[i1] = h1;  g_c[i1] = h1;
    split2_store(h0, g_h2, (size_t)i0, PLANE_H);
    split2_store(h1, g_h2, (size_t)i1, PLANE_H);
    size_t zr = (size_t)b * KZ + 1024;
    split2_store(h0, g_z2, zr + 2 * t,     PLANE_Z);
    split2_store(h1, g_z2, zr + 2 * t + 1, PLANE_Z);
}

__global__ void zero_kernel(float4* __restrict__ p, int n4) {
    for (int i = blockIdx.x * blockDim.x + threadIdx.x; i < n4; i += gridDim.x * blockDim.x)
        p[i] = make_float4(0.f, 0.f, 0.f, 0.f);
}

// ================= generic fused-limb HMMA GEMM body =================
#define ASTAGE (256 * 128)
#define BSTAGE (64 * 128)
#define STAGE_BYTES (ASTAGE + 2 * BSTAGE)
#define SMEM_HMMA (2 * STAGE_BYTES + 128)

__device__ __forceinline__ void gemm_body(
    const __half* __restrict__ Ab, const __half* __restrict__ Bb,
    int lda, int ldb, size_t planeA, size_t planeB, int Kloop,
    const float* __restrict__ bias, float* __restrict__ out,
    int ldo, int Nvalid, unsigned long long* amax,
    int n0, int z, int zs, char* dyn_raw) {

    char* sbase = (char*)(((uintptr_t)dyn_raw + 127) & ~(uintptr_t)127);
    uint32_t sb = smem_u32(sbase);

    int tid = threadIdx.x, lane = tid & 31, warp = tid >> 5;
    int warpM = warp >> 1, warpN = warp & 1;

    const int KC = Kloop >> 6;
    const int F  = 2 * KC;
    const int NCb = (F - z + zs - 1) / zs;

    int rAl[4], rBl[2];
#pragma unroll
    for (int mt = 0; mt < 4; mt++)
        rAl[mt] = warpM * 64 + mt * 16 + (lane & 7) + ((lane >> 3) & 1) * 8;
#pragma unroll
    for (int nt = 0; nt < 2; nt++)
        rBl[nt] = warpN * 32 + nt * 16 + (lane & 7) + (lane >> 4) * 8;
    int clA = lane >> 4;
    int clB = (lane >> 3) & 1;

    int liA_r[8], liA_c[8], liB_r[2], liB_c[2];
#pragma unroll
    for (int i = 0; i < 8; i++) { int li = i * 256 + tid; liA_r[i] = li >> 3; liA_c[i] = li & 7; }
#pragma unroll
    for (int i = 0; i < 2; i++) { int li = i * 256 + tid; liB_r[i] = li >> 3; liB_c[i] = li & 7; }

    auto issue_chunk = [&](int f, int stg) {
        int aL = (f < KC) ? 0 : 1;
        int kb = ((f < KC) ? f : f - KC) << 6;
        const __half* Ap = Ab + (size_t)aL * planeA + kb;
        uint32_t dA  = sb + stg * STAGE_BYTES;
        uint32_t dBh = dA + ASTAGE;
        uint32_t dBm = dBh + BSTAGE;
#pragma unroll
        for (int i = 0; i < 8; i++) {
            int r = liA_r[i], c = liA_c[i];
            cp_async16(dA + r * 128 + ((c ^ (r & 7)) << 4),
                       Ap + (size_t)r * lda + c * 8);
        }
        const __half* Bph = Bb + kb;
#pragma unroll
        for (int i = 0; i < 2; i++) {
            int r = liB_r[i], c = liB_c[i];
            cp_async16(dBh + r * 128 + ((c ^ (r & 7)) << 4),
                       Bph + (size_t)(n0 + r) * ldb + c * 8);
        }
        if (f < KC) {
            const __half* Bpm = Bb + planeB + kb;
#pragma unroll
            for (int i = 0; i < 2; i++) {
                int r = liB_r[i], c = liB_c[i];
                cp_async16(dBm + r * 128 + ((c ^ (r & 7)) << 4),
                           Bpm + (size_t)(n0 + r) * ldb + c * 8);
            }
        }
        CP_COMMIT();
    };

    float acc[4][4][4];
#pragma unroll
    for (int a = 0; a < 4; a++)
#pragma unroll
        for (int b = 0; b < 4; b++)
#pragma unroll
            for (int c = 0; c < 4; c++) acc[a][b][c] = 0.f;

    issue_chunk(z, 0);
    if (NCb > 1) issue_chunk(z + zs, 1);

    for (int i = 0; i < NCb; i++) {
        int f = z + i * zs;
        if (i + 1 < NCb) { CP_WAIT1(); } else { CP_WAIT0(); }
        __syncthreads();

        int stg = i & 1;
        uint32_t sAb  = sb + stg * STAGE_BYTES;
        uint32_t sBhb = sAb + ASTAGE;
        uint32_t sBmb = sBhb + BSTAGE;
        bool two = (f < KC);
#pragma unroll
        for (int h = 0; h < 4; h++) {
            uint32_t af[4][4], bfh[2][4];
#pragma unroll
            for (int mt = 0; mt < 4; mt++) {
                int r = rAl[mt];
                int c = (h * 2 + clA) ^ (r & 7);
                ldmatrix_x4(af[mt], sAb + r * 128 + (c << 4));
            }
#pragma unroll
            for (int nt = 0; nt < 2; nt++) {
                int r = rBl[nt];
                int c = (h * 2 + clB) ^ (r & 7);
                ldmatrix_x4(bfh[nt], sBhb + r * 128 + (c << 4));
            }
#pragma unroll
            for (int mt = 0; mt < 4; mt++)
#pragma unroll
                for (int nt = 0; nt < 2; nt++)
#pragma unroll
                    for (int j = 0; j < 2; j++)
                        mma16816(acc[mt][nt * 2 + j], af[mt], bfh[nt][2 * j], bfh[nt][2 * j + 1]);
            if (two) {
                uint32_t bfm[2][4];
#pragma unroll
                for (int nt = 0; nt < 2; nt++) {
                    int r = rBl[nt];
                    int c = (h * 2 + clB) ^ (r & 7);
                    ldmatrix_x4(bfm[nt], sBmb + r * 128 + (c << 4));
                }
#pragma unroll
                for (int mt = 0; mt < 4; mt++)
#pragma unroll
                    for (int nt = 0; nt < 2; nt++)
#pragma unroll
                        for (int j = 0; j < 2; j++)
                            mma16816(acc[mt][nt * 2 + j], af[mt], bfm[nt][2 * j], bfm[nt][2 * j + 1]);
            }
        }
        __syncthreads();
        if (i + 2 < NCb) issue_chunk(z + (i + 2) * zs, stg);
    }

#pragma unroll
    for (int mt = 0; mt < 4; mt++) {
        int row0 = warpM * 64 + mt * 16 + (lane >> 2);
        unsigned long long k0 = 0ull, k1 = 0ull;
#pragma unroll
        for (int n8 = 0; n8 < 4; n8++) {
            int col = n0 + warpN * 32 + n8 * 8 + (lane & 3) * 2;
            if (col < Nvalid) {
                float bx = bias ? bias[col] : 0.f;
                float by = bias ? bias[col + 1] : 0.f;
                float v0 = acc[mt][n8][0] + bx, v1 = acc[mt][n8][1] + by;
                float v2 = acc[mt][n8][2] + bx, v3 = acc[mt][n8][3] + by;
                *(float2*)(out + (size_t)row0 * ldo + col)       = make_float2(v0, v1);
                *(float2*)(out + (size_t)(row0 + 8) * ldo + col) = make_float2(v2, v3);
                if (amax) {
                    unsigned long long ka = pack_key(v0, col), kb2 = pack_key(v1, col + 1);
                    k0 = k0 > ka ? k0 : ka; k0 = k0 > kb2 ? k0 : kb2;
                    ka = pack_key(v2, col); kb2 = pack_key(v3, col + 1);
                    k1 = k1 > ka ? k1 : ka; k1 = k1 > kb2 ? k1 : kb2;
                }
            }
        }
        if (amax) {
#pragma unroll
            for (int o = 1; o <= 2; o <<= 1) {
                unsigned long long t0 = __shfl_xor_sync(0xFFFFFFFFu, k0, o);
                unsigned long long t1 = __shfl_xor_sync(0xFFFFFFFFu, k1, o);
                k0 = k0 > t0 ? k0 : t0;
                k1 = k1 > t1 ? k1 : t1;
            }
            if ((lane & 3) == 0) {
                if (k0) atomicMax(&amax[row0], k0);
                if (k1) atomicMax(&amax[row0 + 8], k1);
            }
        }
    }
}

// ---------------- attn block body ----------------
__device__ void attn_block_body(const float* __restrict__ enc,
                                const int* __restrict__ counts,
                                int b, unsigned int hwTarget, char* dyn) {
    int t = threadIdx.x;
    int lane = t & 31, w = t >> 5;
    float* hws = (float*)dyn;
    float* sc  = hws + EDIM;
    float* red = sc + CMAX;

    spin_until(&g_sync[0], hwTarget);

    {
        float s0 = g_hwP[0 * BATCH * EDIM + b * EDIM + t]
                 + g_hwP[1 * BATCH * EDIM + b * EDIM + t]
                 + g_hwP[2 * BATCH * EDIM + b * EDIM + t]
                 + g_hwP[3 * BATCH * EDIM + b * EDIM + t];
        float s1 = g_hwP[0 * BATCH * EDIM + b * EDIM + t + 256]
                 + g_hwP[1 * BATCH * EDIM + b * EDIM + t + 256]
                 + g_hwP[2 * BATCH * EDIM + b * EDIM + t + 256]
                 + g_hwP[3 * BATCH * EDIM + b * EDIM + t + 256];
        hws[t] = s0;
        hws[t + 256] = s1;
    }
    __syncthreads();

    int cnt = counts[b], off = g_off[b];

    for (int c = w; c < cnt; c += 8) {
        const float* row = enc + (size_t)(off + c) * EDIM;
        float s = 0.f;
#pragma unroll
        for (int j = 0; j < EDIM; j += 128) {
            float4 v = *(const float4*)(row + j + lane * 4);
            s += v.x * hws[j + lane * 4]     + v.y * hws[j + lane * 4 + 1]
               + v.z * hws[j + lane * 4 + 2] + v.w * hws[j + lane * 4 + 3];
        }
#pragma unroll
        for (int o = 16; o; o >>= 1) s += __shfl_xor_sync(0xFFFFFFFFu, s, o);
        if (lane == 0) sc[c] = s;
    }
    __syncthreads();

    float m = -3.4e38f;
    for (int c = t; c < cnt; c += 256) m = fmaxf(m, sc[c]);
    red[t] = m;
    __syncthreads();
    for (int d = 128; d; d >>= 1) {
        if (t < d) red[t] = fmaxf(red[t], red[t + d]);
        __syncthreads();
    }
    float mx = red[0];
    __syncthreads();

    float s = 0.f;
    for (int c = t; c < cnt; c += 256) {
        float e = expf(sc[c] - mx);
        sc[c] = e;
        s += e;
    }
    red[t] = s;
    __syncthreads();
    for (int d = 128; d; d >>= 1) {
        if (t < d) red[t] += red[t + d];
        __syncthreads();
    }
    float inv = 1.f / red[0];

    float2 a0 = make_float2(0.f, 0.f), a1 = a0, a2 = a0, a3 = a0;
    const float* ebase = enc + (size_t)off * EDIM + 2 * t;
    int c = 0;
    for (; c + 4 <= cnt; c += 4) {
        float w0 = sc[c], w1 = sc[c + 1], w2 = sc[c + 2], w3 = sc[c + 3];
        float2 v0 = *(const float2*)(ebase + (size_t)c * EDIM);
        float2 v1 = *(const float2*)(ebase + (size_t)(c + 1) * EDIM);
        float2 v2 = *(const float2*)(ebase + (size_t)(c + 2) * EDIM);
        float2 v3 = *(const float2*)(ebase + (size_t)(c + 3) * EDIM);
        a0.x += w0 * v0.x; a0.y += w0 * v0.y;
        a1.x += w1 * v1.x; a1.y += w1 * v1.y;
        a2.x += w2 * v2.x; a2.y += w2 * v2.y;
        a3.x += w3 * v3.x; a3.y += w3 * v3.y;
    }
    for (; c < cnt; c++) {
        float w0 = sc[c];
        float2 v0 = *(const float2*)(ebase + (size_t)c * EDIM);
        a0.x += w0 * v0.x; a0.y += w0 * v0.y;
    }
    float ax = ((a0.x + a1.x) + (a2.x + a3.x)) * inv;
    float ay = ((a0.y + a1.y) + (a2.y + a3.y)) * inv;

    size_t zr = (size_t)b * KZ;
    split2_store(ax, g_z2, zr + 512 + 2 * t,     PLANE_Z);
    split2_store(ay, g_z2, zr + 512 + 2 * t + 1, PLANE_Z);

    signal_done(&g_sync[1]);
}

// ================= mega kernel: whole decode step in one launch =================
// segments: [hw 32][attn 256][logits nLog][gates_attth 96][emb_z 32][gates_emb 64][lstm 64]
__global__ void __launch_bounds__(256, 2) mega_kernel(
    float* __restrict__ logits_out, const float* __restrict__ proj_b,
    unsigned long long* amax, int nLog, unsigned int step, unsigned int logCum,
    const float* __restrict__ emb,
    const float* __restrict__ enc, const int* __restrict__ counts) {

    extern __shared__ char dyn_raw[];
    int bx = blockIdx.x;
    int tid = threadIdx.x;

    if (bx < NHW) {
        int z = bx >> 3, n0 = (bx & 7) * 64;
        gemm_body(g_h2, g_AW2, EDIM, EDIM, PLANE_H, PLANE_AW, EDIM,
                  nullptr, g_hwP + (size_t)z * BATCH * EDIM, EDIM, EDIM,
                  nullptr, n0, z, 4, dyn_raw);
        signal_done(&g_sync[0]);
        return;
    }
    bx -= NHW;
    if (bx < NATTN) {
        attn_block_body(enc, counts, bx, step * NHW, dyn_raw);
        return;
    }
    bx -= NATTN;
    if (bx < nLog) {
        gemm_body(g_h2, g_B2, EDIM, EDIM, PLANE_H, PLANE_B, EDIM,
                  proj_b, logits_out, VDIM, VDIM, amax, bx * 64, 0, 1, dyn_raw);
        signal_done(&g_sync[2]);
        return;
    }
    bx -= nLog;
    if (bx < NGATT) {
        int z = bx >> 5, n0 = (bx & 31) * 64;
        spin_until(&g_sync[1], step * NATTN);
        gemm_body(g_z2 + 512, g_W2 + 512, KZ, KZ, PLANE_Z, PLANE_W, 1024,
                  nullptr, g_gatesP + (size_t)z * BATCH * GDIM, GDIM, GDIM,
                  nullptr, n0, z, 3, dyn_raw);
        signal_done(&g_sync[4]);
        return;
    }
    bx -= NGATT;
    if (bx < NEMBZ) {
        spin_until(&g_sync[2], logCum);   // amax finalized
        for (int k = bx * 256 + tid; k < BATCH * EDIM; k += NEMBZ * 256) {
            int b = k >> 9, e = k & 511;
            int tok = 0x7FFFFFFF - (int)(uint32_t)(g_amax[b] & 0xFFFFFFFFull);
            split2_store(emb[(size_t)tok * EDIM + e], g_z2, (size_t)b * KZ + e, PLANE_Z);
        }
        signal_done(&g_sync[3]);
        return;
    }
    bx -= NEMBZ;
    if (bx < NGEMB) {
        int z = bx >> 5, n0 = (bx & 31) * 64;
        spin_until(&g_sync[3], step * NEMBZ);
        gemm_body(g_z2, g_W2, KZ, KZ, PLANE_Z, PLANE_W, EDIM,
                  nullptr, g_gatesP + (size_t)(3 + z) * BATCH * GDIM,
                  GDIM, GDIM, nullptr, n0, z, 2, dyn_raw);
        signal_done(&g_sync[4]);
        return;
    }
    bx -= NGEMB;
    if (bx < NLSTM) {
        spin_until(&g_sync[4], step * NGATES_ALL);
        const size_t P = (size_t)BATCH * GDIM;
        for (int idx = bx * 256 + tid; idx < BATCH * EDIM; idx += NLSTM * 256) {
            int b = idx >> 9, e = idx & 511;
            const float* g0 = g_gatesP + (size_t)b * GDIM;
            float gi = g_bg[e],        gf = g_bg[512 + e];
            float gg = g_bg[1024 + e], go = g_bg[1536 + e];
#pragma unroll
            for (int p = 0; p < 5; p++) {
                gi += g0[p * P + e];
                gf += g0[p * P + 512 + e];
                gg += g0[p * P + 1024 + e];
                go += g0[p * P + 1536 + e];
            }
            float si = 1.f / (1.f + expf(-gi));
            float sf = 1.f / (1.f + expf(-gf));
            float so = 1.f / (1.f + expf(-go));
            float cn = sf * g_c[idx] + si * tanhf(gg);
            float hn = so * tanhf(cn);
            g_c[idx] = cn;
            g_h[idx] = hn;
            split2_store(hn, g_h2, (size_t)idx, PLANE_H);
            split2_store(hn, g_z2, (size_t)b * KZ + 1024 + e, PLANE_Z);
        }
        // reset amax for the next step's logits (emb_z already consumed it)
        if (bx == 0 && tid < BATCH) g_amax[tid] = 0ull;
    }
}

// ---------------- final logits only (step 15) ----------------
__global__ void __launch_bounds__(256, 2) logits_only_kernel(
    float* __restrict__ logits_out, const float* __restrict__ proj_b) {
    extern __shared__ char dyn_raw[];
    gemm_body(g_h2, g_B2, EDIM, EDIM, PLANE_H, PLANE_B, EDIM,
              proj_b, logits_out, VDIM, VDIM, nullptr, blockIdx.x * 64, 0, 1, dyn_raw);
}

// ---------------- launch ----------------
extern "C" void kernel_launch(void* const* d_in, const int* in_sizes, int n_in,
                              void* d_out, int out_size) {
    const float* enc    = (const float*)d_in[0];
    const int*   tl     = (const int*)d_in[1];
    const int*   counts = (const int*)d_in[2];
    const float* emb    = (const float*)d_in[3];
    const float* attn_W = (const float*)d_in[4];
    // d_in[5] = attn_b : drops out (softmax shift invariance)
    const float* W_ih   = (const float*)d_in[6];
    const float* W_hh   = (const float*)d_in[7];
    const float* b_ih   = (const float*)d_in[8];
    const float* b_hh   = (const float*)d_in[9];
    const float* proj_W = (const float*)d_in[10];
    const float* proj_b = (const float*)d_in[11];
    float* out = (float*)d_out;

    unsigned long long* pAmax;
    cudaGetSymbolAddress((void**)&pAmax, g_amax);

    cudaFuncSetAttribute(mega_kernel,
                         cudaFuncAttributeMaxDynamicSharedMemorySize, SMEM_HMMA);
    cudaFuncSetAttribute(logits_only_kernel,
                         cudaFuncAttributeMaxDynamicSharedMemorySize, SMEM_HMMA);

    zero_kernel<<<2048, 256>>>((float4*)out, BATCH * VDIM / 4);
    init_meta_kernel<<<1, BATCH>>>(counts, tl);
    build_wg2_kernel<<<(GDIM * KZ + 255) / 256, 256>>>(W_ih, W_hh, b_ih, b_hh);
    {
        dim3 grid(VPAD / 32, EDIM / 32);
        prepB2_kernel<<<grid, dim3(32, 8)>>>(proj_W);
    }
    prepAW2_kernel<<<(EDIM * EDIM + 255) / 256, 256>>>(attn_W);
    init_h_kernel<<<BATCH, 256>>>(enc, counts);

    // one kernel per decode step
    unsigned int logCum = 0;
    for (unsigned int t = 1; t < LSTEPS; t++) {
        int nlog = (t >= 2) ? NLOG : 0;
        logCum += (unsigned int)nlog;
        float* logits = out + (size_t)(t - 1) * BATCH * VDIM;
        int grid = NHW + NATTN + nlog + NGATT + NEMBZ + NGEMB + NLSTM;
        mega_kernel<<<grid, 256, SMEM_HMMA>>>(
            logits, proj_b, (t >= 2) ? pAmax : nullptr,
            nlog, t, logCum, emb, enc, counts);
    }
    {   // final logits (step 15), no argmax needed
        float* logits = out + (size_t)(LSTEPS - 1) * BATCH * VDIM;
        logits_only_kernel<<<NLOG, 256, SMEM_HMMA>>>(logits, proj_b);
    }
}